// round 2
// baseline (speedup 1.0000x reference)
#include <cuda_runtime.h>
#include <float.h>
#include <math.h>

// Problem constants
#define BB 8
#define NN 1024
#define DD 512
#define M_TOT (BB*NN)   // 8192

// ---------------- scratch (static device globals; no allocation) ----------------
__device__ int   g_type[M_TOT];
__device__ int   g_perm[M_TOT];
__device__ int   g_group[4];
__device__ float g_node_in [M_TOT*DD];
__device__ float g_node_out[M_TOT*DD];
__device__ float g_h_in [M_TOT*DD];
__device__ float g_h_out[M_TOT*DD];
__device__ float g_r[M_TOT*DD];
__device__ float g_z[M_TOT*DD];
__device__ float g_sq[2*M_TOT];   // [dir*8192 + row], dir0 = in
__device__ float g_sv[2*M_TOT];
__device__ float g_m [2*M_TOT];
__device__ float g_il[2*M_TOT];

// ---------------- prep: dtype-detect node_type, convert, counting sort ----------
__global__ void k_prep(const int* __restrict__ ntw)
{
    __shared__ int s_flag;
    __shared__ int s_cnt[1024*3];
    __shared__ int s_tot[3];
    int tid = threadIdx.x;
    if (tid == 0) s_flag = 0;
    __syncthreads();
    // If node_type is int64 (little-endian, values 0..4), all odd 32-bit words
    // of the first 8192 words are zero. Both layouts have >= 8192 words.
    int bad = 0;
    for (int i = tid; i < 4096; i += 1024)
        if (ntw[2*i+1] != 0) bad = 1;
    if (bad) atomicOr(&s_flag, 1);
    __syncthreads();
    int is64 = (s_flag == 0);

    int tv[8];
    int c0 = 0, c1 = 0, c2 = 0;
    for (int k = 0; k < 8; k++) {
        int idx = tid*8 + k;
        int v = is64 ? ntw[2*idx] : ntw[idx];
        int t = (v >= 2 && v <= 4) ? (v - 2) : -1;
        tv[k] = t;
        g_type[idx] = t;
        if (t == 0) c0++; else if (t == 1) c1++; else if (t == 2) c2++;
    }
    s_cnt[tid*3+0] = c0; s_cnt[tid*3+1] = c1; s_cnt[tid*3+2] = c2;
    __syncthreads();
    if (tid < 3) {
        int run = 0;
        for (int i = 0; i < 1024; i++) {
            int c = s_cnt[i*3+tid]; s_cnt[i*3+tid] = run; run += c;
        }
        s_tot[tid] = run;
    }
    __syncthreads();
    if (tid == 0) {
        g_group[0] = 0;
        g_group[1] = s_tot[0];
        g_group[2] = s_tot[0] + s_tot[1];
        g_group[3] = s_tot[0] + s_tot[1] + s_tot[2];
    }
    int b0 = s_cnt[tid*3+0];
    int b1 = s_tot[0] + s_cnt[tid*3+1];
    int b2 = s_tot[0] + s_tot[1] + s_cnt[tid*3+2];
    for (int k = 0; k < 8; k++) {
        int idx = tid*8 + k;
        int t = tv[k];
        if (t == 0)      g_perm[b0++] = idx;
        else if (t == 1) g_perm[b1++] = idx;
        else if (t == 2) g_perm[b2++] = idx;
    }
}

// ---------------- zero node_in / node_out (untyped rows stay zero) --------------
__global__ void k_zero()
{
    size_t i = (size_t)blockIdx.x * blockDim.x + threadIdx.x; // over 1,048,576 f4
    float4 zz = make_float4(0.f, 0.f, 0.f, 0.f);
    ((float4*)g_node_in)[i]  = zz;
    ((float4*)g_node_out)[i] = zz;
}

// ---------------- type-grouped GEMM: node_in / node_out ------------------------
// C[perm[m]] = nodes[perm[m]] @ W[t],   m in [group[t], group[t+1])
__global__ __launch_bounds__(256) void k_gemm_typed(
    const float* __restrict__ A, const float* __restrict__ Wall, int which)
{
    int t = blockIdx.z;
    int gs = g_group[t], ge = g_group[t+1];
    int mbase = gs + blockIdx.y * 128;
    if (mbase >= ge) return;
    float* C = which ? g_node_out : g_node_in;
    const float* W = Wall + (size_t)t * DD * DD;
    int nbase = blockIdx.x * 128;

    __shared__ float As[8][128];
    __shared__ float Bs[8][132];
    int tid = threadIdx.x;
    int ar = tid >> 1, akq = (tid & 1) * 4;
    int gmr = mbase + ar;
    bool aok = (gmr < ge);
    int arow = aok ? g_perm[gmr] : 0;
    const float* aptr = A + ((size_t)arow << 9) + akq;
    int bkr = tid >> 5, bc = (tid & 31) * 4;
    const float* bptr = W + ((size_t)bkr << 9) + nbase + bc;

    float4 apf = aok ? *(const float4*)aptr : make_float4(0,0,0,0);
    float4 bpf = *(const float4*)bptr;

    int tx = tid & 15, ty = tid >> 4;
    float acc[8][8];
    #pragma unroll
    for (int i = 0; i < 8; i++)
        #pragma unroll
        for (int j = 0; j < 8; j++) acc[i][j] = 0.f;

    const int KT = 64;
    for (int kt = 0; kt < KT; kt++) {
        As[akq+0][ar] = apf.x; As[akq+1][ar] = apf.y;
        As[akq+2][ar] = apf.z; As[akq+3][ar] = apf.w;
        *(float4*)&Bs[bkr][bc] = bpf;
        __syncthreads();
        if (kt + 1 < KT) {
            apf = aok ? *(const float4*)(aptr + (kt+1)*8) : make_float4(0,0,0,0);
            bpf = *(const float4*)(bptr + (size_t)(kt+1)*8*DD);
        }
        #pragma unroll
        for (int kk = 0; kk < 8; kk++) {
            float4 a0 = *(const float4*)&As[kk][ty*8];
            float4 a1 = *(const float4*)&As[kk][ty*8+4];
            float4 b0 = *(const float4*)&Bs[kk][tx*8];
            float4 b1 = *(const float4*)&Bs[kk][tx*8+4];
            float av[8] = {a0.x,a0.y,a0.z,a0.w,a1.x,a1.y,a1.z,a1.w};
            float bv[8] = {b0.x,b0.y,b0.z,b0.w,b1.x,b1.y,b1.z,b1.w};
            #pragma unroll
            for (int i = 0; i < 8; i++)
                #pragma unroll
                for (int j = 0; j < 8; j++)
                    acc[i][j] += av[i] * bv[j];
        }
        __syncthreads();
    }
    #pragma unroll
    for (int i = 0; i < 8; i++) {
        int gm2 = mbase + ty*8 + i;
        if (gm2 < ge) {
            float* cp = C + ((size_t)g_perm[gm2] << 9) + nbase + tx*8;
            *(float4*)cp     = make_float4(acc[i][0],acc[i][1],acc[i][2],acc[i][3]);
            *(float4*)(cp+4) = make_float4(acc[i][4],acc[i][5],acc[i][6],acc[i][7]);
        }
    }
}

// ---------------- per-row dots: s_q (nodes.a_q) and s_v (node_x.a_v) ------------
__device__ __forceinline__ float dot4(float4 a, float4 b) {
    return a.x*b.x + a.y*b.y + a.z*b.z + a.w*b.w;
}
__global__ void k_dots(const float* __restrict__ nodes,
    const float* __restrict__ aqi, const float* __restrict__ avi,
    const float* __restrict__ aqo, const float* __restrict__ avo)
{
    int row = blockIdx.x, tid = threadIdx.x;
    size_t off = ((size_t)row << 9) + tid*4;
    int d = tid*4;
    float4 nv = *(const float4*)(nodes + off);
    float4 ni = *(const float4*)(g_node_in + off);
    float4 no = *(const float4*)(g_node_out + off);
    float s0 = dot4(nv, *(const float4*)(aqi + d));
    float s1 = dot4(ni, *(const float4*)(avi + d));
    float s2 = dot4(nv, *(const float4*)(aqo + d));
    float s3 = dot4(no, *(const float4*)(avo + d));
    #pragma unroll
    for (int o2 = 16; o2; o2 >>= 1) {
        s0 += __shfl_down_sync(0xffffffffu, s0, o2);
        s1 += __shfl_down_sync(0xffffffffu, s1, o2);
        s2 += __shfl_down_sync(0xffffffffu, s2, o2);
        s3 += __shfl_down_sync(0xffffffffu, s3, o2);
    }
    __shared__ float sm[4][4];
    int w = tid >> 5, l = tid & 31;
    if (l == 0) { sm[w][0]=s0; sm[w][1]=s1; sm[w][2]=s2; sm[w][3]=s3; }
    __syncthreads();
    if (tid == 0) {
        float r0=0,r1=0,r2=0,r3=0;
        #pragma unroll
        for (int i = 0; i < 4; i++) { r0+=sm[i][0]; r1+=sm[i][1]; r2+=sm[i][2]; r3+=sm[i][3]; }
        g_sq[row] = r0; g_sv[row] = r1;
        g_sq[M_TOT+row] = r2; g_sv[M_TOT+row] = r3;
    }
}

// ---------------- softmax stats pass (row max m, inv-sum 1/l) -------------------
__global__ void k_score(const int* __restrict__ mask)
{
    int row = blockIdx.x;
    int dir = blockIdx.y;
    int b = row >> 10;
    const float* sv = g_sv + dir*M_TOT;
    const int* mrow = mask + ((size_t)dir*M_TOT + row) * NN;
    float sqi = g_sq[dir*M_TOT + row];
    float tm = -FLT_MAX, tl = 0.f;
    for (int j = threadIdx.x; j < NN; j += 256) {
        float x = sqi + sv[(b<<10) + j];
        float e = (mrow[j] > 0) ? (x >= 0.f ? x : 0.2f*x) : -1e9f;
        if (e > tm) { tl = tl*__expf(tm - e) + 1.f; tm = e; }
        else          tl += __expf(e - tm);
    }
    __shared__ float sm[256], sl[256];
    sm[threadIdx.x] = tm; sl[threadIdx.x] = tl;
    __syncthreads();
    for (int s = 128; s > 0; s >>= 1) {
        if (threadIdx.x < s) {
            float m1 = sm[threadIdx.x], m2 = sm[threadIdx.x+s];
            float l1 = sl[threadIdx.x], l2 = sl[threadIdx.x+s];
            float mm = fmaxf(m1, m2);
            sm[threadIdx.x] = mm;
            sl[threadIdx.x] = l1*__expf(m1-mm) + l2*__expf(m2-mm);
        }
        __syncthreads();
    }
    if (threadIdx.x == 0) {
        g_m [dir*M_TOT + row] = sm[0];
        g_il[dir*M_TOT + row] = 1.f / sl[0];
    }
}

// ---------------- GAT weighted sum: h = P @ v (P generated on the fly) ----------
__global__ __launch_bounds__(256) void k_gat(const int* __restrict__ mask)
{
    int dir = blockIdx.y;
    int row0 = blockIdx.x * 32;
    int b = row0 >> 10;
    const float* v  = dir ? g_node_out : g_node_in;
    const float* sv = g_sv + dir*M_TOT;
    float* hout = dir ? g_h_out : g_h_in;
    const int* mbase = mask + ((size_t)dir*M_TOT + row0) * NN;

    __shared__ float vsm[16*512];           // 32 KB
    __shared__ float psm[32][17];
    __shared__ float s_m[32], s_il[32], s_sq[32], s_svt[16];
    int tid = threadIdx.x;
    if (tid < 32) {
        int rr = row0 + tid;
        s_m [tid] = g_m [dir*M_TOT + rr];
        s_il[tid] = g_il[dir*M_TOT + rr];
        s_sq[tid] = g_sq[dir*M_TOT + rr];
    }
    float2 acc[32];
    #pragma unroll
    for (int r = 0; r < 32; r++) acc[r] = make_float2(0.f, 0.f);
    int c0 = tid * 2;
    const float4* vsrc0 = (const float4*)(v + ((size_t)(b<<10)) * DD);

    for (int jt = 0; jt < 64; jt++) {
        int j0 = jt * 16;
        __syncthreads();
        #pragma unroll
        for (int i = 0; i < 8; i++) {
            int idx = tid + i*256;                  // 0..2047 float4s
            ((float4*)vsm)[idx] = vsrc0[(size_t)j0*128 + idx];
        }
        if (tid < 16) s_svt[tid] = sv[(b<<10) + j0 + tid];
        __syncthreads();
        {
            int jj = tid & 15, r = tid >> 4;        // r 0..15
            #pragma unroll
            for (int h = 0; h < 2; h++) {
                int rr = r + h*16;
                int mv = mbase[(size_t)rr*NN + j0 + jj];
                float x = s_sq[rr] + s_svt[jj];
                float e = (mv > 0) ? (x >= 0.f ? x : 0.2f*x) : -1e9f;
                psm[rr][jj] = __expf(e - s_m[rr]) * s_il[rr];
            }
        }
        __syncthreads();
        #pragma unroll
        for (int jj = 0; jj < 16; jj++) {
            float2 v2 = *(const float2*)&vsm[jj*512 + c0];
            #pragma unroll
            for (int r = 0; r < 32; r++) {
                float p = psm[r][jj];
                acc[r].x += p * v2.x;
                acc[r].y += p * v2.y;
            }
        }
    }
    #pragma unroll
    for (int r = 0; r < 32; r++)
        *(float2*)(hout + (size_t)(row0 + r)*DD + c0) = acc[r];
}

// ---------------- GGNN GEMMs ----------------------------------------------------
__device__ __forceinline__ float4 load_cat(const float* __restrict__ nodes,
                                           int gm, int k0, int akq)
{
    if (k0 < 512)  return *(const float4*)(g_h_in  + ((size_t)gm << 9) + k0 + akq);
    if (k0 < 1024) return *(const float4*)(g_h_out + ((size_t)gm << 9) + k0 - 512 + akq);
    return *(const float4*)(nodes + ((size_t)gm << 9) + k0 - 1024 + akq);
}
__device__ __forceinline__ float4 load_cat_r(const float* __restrict__ nodes,
                                             int gm, int k0, int akq)
{
    if (k0 < 512)  return *(const float4*)(g_h_in  + ((size_t)gm << 9) + k0 + akq);
    if (k0 < 1024) return *(const float4*)(g_h_out + ((size_t)gm << 9) + k0 - 512 + akq);
    float4 nv = *(const float4*)(nodes + ((size_t)gm << 9) + k0 - 1024 + akq);
    float4 rv = *(const float4*)(g_r   + ((size_t)gm << 9) + k0 - 1024 + akq);
    return make_float4(nv.x*rv.x, nv.y*rv.y, nv.z*rv.z, nv.w*rv.w);
}

// r / z : sigmoid([h_in|h_out|nodes] @ W + b)
__global__ __launch_bounds__(256) void k_gemm_gate(
    const float* __restrict__ nodes, const float* __restrict__ W,
    const float* __restrict__ bias, int which)
{
    float* C = which ? g_z : g_r;
    int mbase = blockIdx.y * 128, nbase = blockIdx.x * 128;
    __shared__ float As[8][128];
    __shared__ float Bs[8][132];
    int tid = threadIdx.x;
    int ar = tid >> 1, akq = (tid & 1) * 4;
    int gm = mbase + ar;
    int bkr = tid >> 5, bc = (tid & 31) * 4;
    const float* bptr = W + ((size_t)bkr << 9) + nbase + bc;

    float4 apf = load_cat(nodes, gm, 0, akq);
    float4 bpf = *(const float4*)bptr;

    int tx = tid & 15, ty = tid >> 4;
    float acc[8][8];
    #pragma unroll
    for (int i = 0; i < 8; i++)
        #pragma unroll
        for (int j = 0; j < 8; j++) acc[i][j] = 0.f;

    const int KT = 192;
    for (int kt = 0; kt < KT; kt++) {
        As[akq+0][ar] = apf.x; As[akq+1][ar] = apf.y;
        As[akq+2][ar] = apf.z; As[akq+3][ar] = apf.w;
        *(float4*)&Bs[bkr][bc] = bpf;
        __syncthreads();
        if (kt + 1 < KT) {
            apf = load_cat(nodes, gm, (kt+1)*8, akq);
            bpf = *(const float4*)(bptr + (size_t)(kt+1)*8*DD);
        }
        #pragma unroll
        for (int kk = 0; kk < 8; kk++) {
            float4 a0 = *(const float4*)&As[kk][ty*8];
            float4 a1 = *(const float4*)&As[kk][ty*8+4];
            float4 b0 = *(const float4*)&Bs[kk][tx*8];
            float4 b1 = *(const float4*)&Bs[kk][tx*8+4];
            float av[8] = {a0.x,a0.y,a0.z,a0.w,a1.x,a1.y,a1.z,a1.w};
            float bv[8] = {b0.x,b0.y,b0.z,b0.w,b1.x,b1.y,b1.z,b1.w};
            #pragma unroll
            for (int i = 0; i < 8; i++)
                #pragma unroll
                for (int j = 0; j < 8; j++)
                    acc[i][j] += av[i] * bv[j];
        }
        __syncthreads();
    }
    #pragma unroll
    for (int i = 0; i < 8; i++) {
        int row = mbase + ty*8 + i;
        float* cp = C + ((size_t)row << 9) + nbase + tx*8;
        #pragma unroll
        for (int j = 0; j < 8; j++) {
            float val = acc[i][j] + bias[nbase + tx*8 + j];
            acc[i][j] = 1.f / (1.f + __expf(-val));
        }
        *(float4*)cp     = make_float4(acc[i][0],acc[i][1],acc[i][2],acc[i][3]);
        *(float4*)(cp+4) = make_float4(acc[i][4],acc[i][5],acc[i][6],acc[i][7]);
    }
}

// h_hat + final gating: out = (1-z)*nodes + z*tanh([h_in|h_out|r*nodes]@W_t + b_t)
__global__ __launch_bounds__(256) void k_gemm_final(
    const float* __restrict__ nodes, const float* __restrict__ W,
    const float* __restrict__ bias, float* __restrict__ out)
{
    int mbase = blockIdx.y * 128, nbase = blockIdx.x * 128;
    __shared__ float As[8][128];
    __shared__ float Bs[8][132];
    int tid = threadIdx.x;
    int ar = tid >> 1, akq = (tid & 1) * 4;
    int gm = mbase + ar;
    int bkr = tid >> 5, bc = (tid & 31) * 4;
    const float* bptr = W + ((size_t)bkr << 9) + nbase + bc;

    float4 apf = load_cat_r(nodes, gm, 0, akq);
    float4 bpf = *(const float4*)bptr;

    int tx = tid & 15, ty = tid >> 4;
    float acc[8][8];
    #pragma unroll
    for (int i = 0; i < 8; i++)
        #pragma unroll
        for (int j = 0; j < 8; j++) acc[i][j] = 0.f;

    const int KT = 192;
    for (int kt = 0; kt < KT; kt++) {
        As[akq+0][ar] = apf.x; As[akq+1][ar] = apf.y;
        As[akq+2][ar] = apf.z; As[akq+3][ar] = apf.w;
        *(float4*)&Bs[bkr][bc] = bpf;
        __syncthreads();
        if (kt + 1 < KT) {
            apf = load_cat_r(nodes, gm, (kt+1)*8, akq);
            bpf = *(const float4*)(bptr + (size_t)(kt+1)*8*DD);
        }
        #pragma unroll
        for (int kk = 0; kk < 8; kk++) {
            float4 a0 = *(const float4*)&As[kk][ty*8];
            float4 a1 = *(const float4*)&As[kk][ty*8+4];
            float4 b0 = *(const float4*)&Bs[kk][tx*8];
            float4 b1 = *(const float4*)&Bs[kk][tx*8+4];
            float av[8] = {a0.x,a0.y,a0.z,a0.w,a1.x,a1.y,a1.z,a1.w};
            float bv[8] = {b0.x,b0.y,b0.z,b0.w,b1.x,b1.y,b1.z,b1.w};
            #pragma unroll
            for (int i = 0; i < 8; i++)
                #pragma unroll
                for (int j = 0; j < 8; j++)
                    acc[i][j] += av[i] * bv[j];
        }
        __syncthreads();
    }
    #pragma unroll
    for (int i = 0; i < 8; i++) {
        int row = mbase + ty*8 + i;
        size_t off = ((size_t)row << 9) + nbase + tx*8;
        float4 z0 = *(const float4*)(g_z + off);
        float4 z1 = *(const float4*)(g_z + off + 4);
        float4 n0 = *(const float4*)(nodes + off);
        float4 n1 = *(const float4*)(nodes + off + 4);
        float hz[8] = {z0.x,z0.y,z0.z,z0.w,z1.x,z1.y,z1.z,z1.w};
        float hn[8] = {n0.x,n0.y,n0.z,n0.w,n1.x,n1.y,n1.z,n1.w};
        float o[8];
        #pragma unroll
        for (int j = 0; j < 8; j++) {
            float h = tanhf(acc[i][j] + bias[nbase + tx*8 + j]);
            o[j] = (1.f - hz[j]) * hn[j] + hz[j] * h;
        }
        *(float4*)(out + off)     = make_float4(o[0],o[1],o[2],o[3]);
        *(float4*)(out + off + 4) = make_float4(o[4],o[5],o[6],o[7]);
    }
}

// ---------------- launch --------------------------------------------------------
extern "C" void kernel_launch(void* const* d_in, const int* in_sizes, int n_in,
                              void* d_out, int out_size)
{
    const float* nodes  = (const float*)d_in[0];
    const int*   mask   = (const int*)  d_in[1];
    const int*   ntw    = (const int*)  d_in[2];   // int32 or int64 — detected on device
    const float* W_in   = (const float*)d_in[3];
    const float* W_out  = (const float*)d_in[4];
    const float* a_in_q = (const float*)d_in[5];
    const float* a_in_v = (const float*)d_in[6];
    const float* a_out_q= (const float*)d_in[7];
    const float* a_out_v= (const float*)d_in[8];
    const float* W_r    = (const float*)d_in[9];
    const float* b_r    = (const float*)d_in[10];
    const float* W_z    = (const float*)d_in[11];
    const float* b_z    = (const float*)d_in[12];
    const float* W_t    = (const float*)d_in[13];
    const float* b_t    = (const float*)d_in[14];
    float* out = (float*)d_out;

    k_prep<<<1, 1024>>>(ntw);
    k_zero<<<4096, 256>>>();
    k_gemm_typed<<<dim3(4, 64, 3), 256>>>(nodes, W_in, 0);
    k_gemm_typed<<<dim3(4, 64, 3), 256>>>(nodes, W_out, 1);
    k_dots<<<M_TOT, 128>>>(nodes, a_in_q, a_in_v, a_out_q, a_out_v);
    k_score<<<dim3(M_TOT, 2), 256>>>(mask);
    k_gat<<<dim3(M_TOT/32, 2), 256>>>(mask);
    k_gemm_gate<<<dim3(4, 64), 256>>>(nodes, W_r, b_r, 0);
    k_gemm_gate<<<dim3(4, 64), 256>>>(nodes, W_z, b_z, 1);
    k_gemm_final<<<dim3(4, 64), 256>>>(nodes, W_t, b_t, out);
}

// round 3
// speedup vs baseline: 2.9257x; 2.9257x over previous
#include <cuda_runtime.h>
#include <math.h>

#define M_TOT 8192
#define DD 512

// ---------------- scratch (static device globals) ----------------
__device__ int   g_perm[M_TOT];
__device__ int   g_group[4];
__device__ float g_node_in [M_TOT*DD];
__device__ float g_node_out[M_TOT*DD];
__device__ float g_h_in [M_TOT*DD];
__device__ float g_h_out[M_TOT*DD];
__device__ float g_r[M_TOT*DD];
__device__ float g_z[M_TOT*DD];
__device__ float g_sq[2*M_TOT];
__device__ float g_sv[2*M_TOT];
__device__ float g_eq[2*M_TOT];
__device__ float g_fq[2*M_TOT];
__device__ float g_ev[2*M_TOT];
__device__ float g_fv[2*M_TOT];
__device__ float g_p[2*M_TOT*1024];   // 64MB: normalized attention probs

// ---------------- prep: dtype-detect node_type, counting sort ----------
__global__ void k_prep(const int* __restrict__ ntw)
{
    __shared__ int s_flag;
    __shared__ int s_cnt[1024*3];
    __shared__ int s_tot[3];
    int tid = threadIdx.x;
    if (tid == 0) s_flag = 0;
    __syncthreads();
    int bad = 0;
    for (int i = tid; i < 4096; i += 1024)
        if (ntw[2*i+1] != 0) bad = 1;
    if (bad) atomicOr(&s_flag, 1);
    __syncthreads();
    int is64 = (s_flag == 0);

    int tv[8];
    int c0 = 0, c1 = 0, c2 = 0;
    for (int k = 0; k < 8; k++) {
        int idx = tid*8 + k;
        int v = is64 ? ntw[2*idx] : ntw[idx];
        int t = (v >= 2 && v <= 4) ? (v - 2) : -1;
        tv[k] = t;
        if (t == 0) c0++; else if (t == 1) c1++; else if (t == 2) c2++;
    }
    s_cnt[tid*3+0] = c0; s_cnt[tid*3+1] = c1; s_cnt[tid*3+2] = c2;
    __syncthreads();
    if (tid < 3) {
        int run = 0;
        for (int i = 0; i < 1024; i++) {
            int c = s_cnt[i*3+tid]; s_cnt[i*3+tid] = run; run += c;
        }
        s_tot[tid] = run;
    }
    __syncthreads();
    if (tid == 0) {
        g_group[0] = 0;
        g_group[1] = s_tot[0];
        g_group[2] = s_tot[0] + s_tot[1];
        g_group[3] = s_tot[0] + s_tot[1] + s_tot[2];
    }
    int b0 = s_cnt[tid*3+0];
    int b1 = s_tot[0] + s_cnt[tid*3+1];
    int b2 = s_tot[0] + s_tot[1] + s_cnt[tid*3+2];
    for (int k = 0; k < 8; k++) {
        int idx = tid*8 + k;
        int t = tv[k];
        if (t == 0)      g_perm[b0++] = idx;
        else if (t == 1) g_perm[b1++] = idx;
        else if (t == 2) g_perm[b2++] = idx;
    }
}

__global__ void k_zero()
{
    size_t i = (size_t)blockIdx.x * blockDim.x + threadIdx.x;
    float4 zz = make_float4(0.f, 0.f, 0.f, 0.f);
    ((float4*)g_node_in)[i]  = zz;
    ((float4*)g_node_out)[i] = zz;
}

// ---------------- per-row dots + factored exps ------------------------
__device__ __forceinline__ float dot4(float4 a, float4 b) {
    return a.x*b.x + a.y*b.y + a.z*b.z + a.w*b.w;
}
__global__ void k_dots(const float* __restrict__ nodes,
    const float* __restrict__ aqi, const float* __restrict__ avi,
    const float* __restrict__ aqo, const float* __restrict__ avo)
{
    int row = blockIdx.x, tid = threadIdx.x;
    size_t off = ((size_t)row << 9) + tid*4;
    int d = tid*4;
    float4 nv = *(const float4*)(nodes + off);
    float4 ni = *(const float4*)(g_node_in + off);
    float4 no = *(const float4*)(g_node_out + off);
    float s0 = dot4(nv, *(const float4*)(aqi + d));
    float s1 = dot4(ni, *(const float4*)(avi + d));
    float s2 = dot4(nv, *(const float4*)(aqo + d));
    float s3 = dot4(no, *(const float4*)(avo + d));
    #pragma unroll
    for (int o2 = 16; o2; o2 >>= 1) {
        s0 += __shfl_down_sync(0xffffffffu, s0, o2);
        s1 += __shfl_down_sync(0xffffffffu, s1, o2);
        s2 += __shfl_down_sync(0xffffffffu, s2, o2);
        s3 += __shfl_down_sync(0xffffffffu, s3, o2);
    }
    __shared__ float sm[4][4];
    int w = tid >> 5, l = tid & 31;
    if (l == 0) { sm[w][0]=s0; sm[w][1]=s1; sm[w][2]=s2; sm[w][3]=s3; }
    __syncthreads();
    if (tid == 0) {
        float r0=0,r1=0,r2=0,r3=0;
        #pragma unroll
        for (int i = 0; i < 4; i++) { r0+=sm[i][0]; r1+=sm[i][1]; r2+=sm[i][2]; r3+=sm[i][3]; }
        g_sq[row] = r0; g_sv[row] = r1;
        g_sq[M_TOT+row] = r2; g_sv[M_TOT+row] = r3;
        g_eq[row] = __expf(r0);        g_fq[row] = __expf(0.2f*r0);
        g_ev[row] = __expf(r1);        g_fv[row] = __expf(0.2f*r1);
        g_eq[M_TOT+row] = __expf(r2);  g_fq[M_TOT+row] = __expf(0.2f*r2);
        g_ev[M_TOT+row] = __expf(r3);  g_fv[M_TOT+row] = __expf(0.2f*r3);
    }
}

// ---------------- P: normalized attention probabilities ----------------
// w_ij = mask ? (s>=0 ? Eq_i*Ev_j : Fq_i*Fv_j) : 0 ; P = w / sum_j w
__global__ __launch_bounds__(256) void k_p(const int* __restrict__ mask)
{
    int row = blockIdx.x, dir = blockIdx.y;
    int b = row >> 10;
    int tid = threadIdx.x;
    size_t base = ((size_t)(dir*M_TOT + row)) << 10;
    int gi = dir*M_TOT + row;
    float sq = g_sq[gi], Eq = g_eq[gi], Fq = g_fq[gi];
    int jb = dir*M_TOT + (b << 10);
    int4   mv = ((const int4*)(mask + base))[tid];
    float4 sv = ((const float4*)(g_sv + jb))[tid];
    float4 ev = ((const float4*)(g_ev + jb))[tid];
    float4 fv = ((const float4*)(g_fv + jb))[tid];
    float w0 = (mv.x > 0) ? ((sq + sv.x >= 0.f) ? Eq*ev.x : Fq*fv.x) : 0.f;
    float w1 = (mv.y > 0) ? ((sq + sv.y >= 0.f) ? Eq*ev.y : Fq*fv.y) : 0.f;
    float w2 = (mv.z > 0) ? ((sq + sv.z >= 0.f) ? Eq*ev.z : Fq*fv.z) : 0.f;
    float w3 = (mv.w > 0) ? ((sq + sv.w >= 0.f) ? Eq*ev.w : Fq*fv.w) : 0.f;
    float s = w0 + w1 + w2 + w3;
    #pragma unroll
    for (int o = 16; o; o >>= 1) s += __shfl_xor_sync(0xffffffffu, s, o);
    __shared__ float swarp[8];
    __shared__ float sinv;
    if ((tid & 31) == 0) swarp[tid >> 5] = s;
    __syncthreads();
    if (tid < 8) {
        float v = swarp[tid];
        #pragma unroll
        for (int o = 4; o; o >>= 1) v += __shfl_xor_sync(0xffu, v, o);
        if (tid == 0) sinv = 1.f / v;
    }
    __syncthreads();
    float inv = sinv;
    ((float4*)(g_p + base))[tid] = make_float4(w0*inv, w1*inv, w2*inv, w3*inv);
}

// ---------------- tf32 tensor-core GEMM core ---------------------------
__device__ __forceinline__ float f2t(float x) {
    unsigned r;
    asm("cvt.rna.tf32.f32 %0, %1;" : "=r"(r) : "f"(x));
    return __uint_as_float(r);
}
__device__ __forceinline__ float4 cvt4(float4 v) {
    return make_float4(f2t(v.x), f2t(v.y), f2t(v.z), f2t(v.w));
}
__device__ __forceinline__ void mma8(float* c, const float* a, const float* b) {
    asm volatile(
        "mma.sync.aligned.m16n8k8.row.col.f32.tf32.tf32.f32 "
        "{%0,%1,%2,%3}, {%4,%5,%6,%7}, {%8,%9}, {%0,%1,%2,%3};\n"
        : "+f"(c[0]), "+f"(c[1]), "+f"(c[2]), "+f"(c[3])
        : "r"(__float_as_uint(a[0])), "r"(__float_as_uint(a[1])),
          "r"(__float_as_uint(a[2])), "r"(__float_as_uint(a[3])),
          "r"(__float_as_uint(b[0])), "r"(__float_as_uint(b[1])));
}

// MODE 0: typed linear (A gathered via perm, C scattered via perm), K=512
// MODE 1: gate r/z : sigmoid([h_in|h_out|nodes]@W + b), K=1536
// MODE 2: final    : out = (1-z)*nodes + z*tanh([h_in|h_out|r*nodes]@W + b), K=1536
// MODE 3: GAT      : h = P @ V per (dir,batch), K=1024
template<int MODE>
__global__ __launch_bounds__(512) void k_mma(
    const float* __restrict__ A_, const float* __restrict__ Bsrc,
    const float* __restrict__ bias, float* __restrict__ Cout, int which)
{
    constexpr int KIT = (MODE == 0) ? 16 : (MODE == 3) ? 32 : 48;
    __shared__ float As[128*36];    // As[m*36 + k]
    __shared__ float Bs[32*136];    // Bs[k*136 + n]

    int tid = threadIdx.x;
    int nbase = blockIdx.x * 128;
    int am = tid >> 3, akq = tid & 7;     // A staging: rows am, am+64; k-quad akq
    int bk = tid >> 5, bnq = tid & 31;    // B staging: k rows bk, bk+16; n-quad bnq

    int mbase = blockIdx.y * 128;
    int ge = 1 << 30;
    const float* Bp = Bsrc;
    float* C = Cout;
    // plain A row pointers (MODE 0/3)
    const float *pa0 = nullptr, *pa1 = nullptr;
    // concat A row pointers (MODE 1/2)
    const float *hi0 = nullptr, *hi1 = nullptr, *ho0 = nullptr, *ho1 = nullptr;
    const float *nd0 = nullptr, *nd1 = nullptr, *rr0 = nullptr, *rr1 = nullptr;

    if (MODE == 0) {
        int t = blockIdx.z;
        int gs = g_group[t]; ge = g_group[t+1];
        mbase = gs + blockIdx.y * 128;
        if (mbase >= ge) return;
        Bp = Bsrc + (size_t)t * DD * DD;
        C = which ? g_node_out : g_node_in;
        int r0i = mbase + am, r1i = mbase + am + 64;
        pa0 = (r0i < ge) ? (A_ + ((size_t)g_perm[r0i] << 9)) : nullptr;
        pa1 = (r1i < ge) ? (A_ + ((size_t)g_perm[r1i] << 9)) : nullptr;
    } else if (MODE == 1 || MODE == 2) {
        size_t o0 = (size_t)(mbase + am) << 9;
        size_t o1 = (size_t)(mbase + am + 64) << 9;
        hi0 = g_h_in + o0;  hi1 = g_h_in + o1;
        ho0 = g_h_out + o0; ho1 = g_h_out + o1;
        nd0 = A_ + o0;      nd1 = A_ + o1;
        if (MODE == 2) { rr0 = g_r + o0; rr1 = g_r + o1; }
        if (MODE == 1) C = which ? g_z : g_r;
    } else { // MODE 3
        int dir = blockIdx.z >> 3, b = blockIdx.z & 7;
        const float* Pa = g_p + (((size_t)(dir*M_TOT + (b << 10) + mbase)) << 10);
        pa0 = Pa + ((size_t)am << 10);
        pa1 = Pa + ((size_t)(am + 64) << 10);
        Bp = (dir ? g_node_out : g_node_in) + (((size_t)(b << 10)) << 9);
        C  = (dir ? g_h_out  : g_h_in) + (((size_t)(b << 10)) << 9);
    }

    // fragment ids
    int lane = tid & 31, g = lane >> 2, tg = lane & 3;
    int wid = tid >> 5;
    int wm = (wid >> 2) * 32, wn = (wid & 3) * 32;

    float acc[2][4][4];
    #pragma unroll
    for (int mi = 0; mi < 2; mi++)
        #pragma unroll
        for (int ni = 0; ni < 4; ni++)
            #pragma unroll
            for (int q = 0; q < 4; q++) acc[mi][ni][q] = 0.f;

    float4 va0, va1, vb0, vb1;
    const float4 z4 = make_float4(0.f, 0.f, 0.f, 0.f);

    // ---- load for tile kt into regs
    auto loadA = [&](int kt, float4& a0, float4& a1) {
        int col = kt*32 + akq*4;
        if (MODE == 0) {
            a0 = pa0 ? *(const float4*)(pa0 + col) : z4;
            a1 = pa1 ? *(const float4*)(pa1 + col) : z4;
        } else if (MODE == 3) {
            a0 = *(const float4*)(pa0 + col);
            a1 = *(const float4*)(pa1 + col);
        } else {
            int seg = col >> 9, off = col & 511;
            if (seg == 0)      { a0 = *(const float4*)(hi0 + off); a1 = *(const float4*)(hi1 + off); }
            else if (seg == 1) { a0 = *(const float4*)(ho0 + off); a1 = *(const float4*)(ho1 + off); }
            else {
                a0 = *(const float4*)(nd0 + off); a1 = *(const float4*)(nd1 + off);
                if (MODE == 2) {
                    float4 r0 = *(const float4*)(rr0 + off), r1 = *(const float4*)(rr1 + off);
                    a0.x*=r0.x; a0.y*=r0.y; a0.z*=r0.z; a0.w*=r0.w;
                    a1.x*=r1.x; a1.y*=r1.y; a1.z*=r1.z; a1.w*=r1.w;
                }
            }
        }
    };
    auto loadB = [&](int kt, float4& b0, float4& b1) {
        size_t r0 = (size_t)(kt*32 + bk) * DD + nbase + bnq*4;
        b0 = *(const float4*)(Bp + r0);
        b1 = *(const float4*)(Bp + r0 + (size_t)16*DD);
    };

    loadA(0, va0, va1);
    loadB(0, vb0, vb1);

    for (int kt = 0; kt < KIT; kt++) {
        __syncthreads();
        *(float4*)&As[am*36 + akq*4]        = cvt4(va0);
        *(float4*)&As[(am+64)*36 + akq*4]   = cvt4(va1);
        *(float4*)&Bs[bk*136 + bnq*4]       = cvt4(vb0);
        *(float4*)&Bs[(bk+16)*136 + bnq*4]  = cvt4(vb1);
        __syncthreads();
        if (kt + 1 < KIT) { loadA(kt+1, va0, va1); loadB(kt+1, vb0, vb1); }

        #pragma unroll
        for (int ks = 0; ks < 4; ks++) {
            int k0 = ks*8;
            float a[2][4], bf[4][2];
            #pragma unroll
            for (int mi = 0; mi < 2; mi++) {
                int mr = wm + mi*16 + g;
                a[mi][0] = As[mr*36     + k0 + tg];
                a[mi][1] = As[(mr+8)*36 + k0 + tg];
                a[mi][2] = As[mr*36     + k0 + tg + 4];
                a[mi][3] = As[(mr+8)*36 + k0 + tg + 4];
            }
            #pragma unroll
            for (int ni = 0; ni < 4; ni++) {
                bf[ni][0] = Bs[(k0+tg)*136   + wn + ni*8 + g];
                bf[ni][1] = Bs[(k0+tg+4)*136 + wn + ni*8 + g];
            }
            #pragma unroll
            for (int mi = 0; mi < 2; mi++)
                #pragma unroll
                for (int ni = 0; ni < 4; ni++)
                    mma8(acc[mi][ni], a[mi], bf[ni]);
        }
    }

    // ---- epilogue
    #pragma unroll
    for (int mi = 0; mi < 2; mi++) {
        int rA = mbase + wm + mi*16 + g;
        int rB = rA + 8;
        int pA = rA, pB = rB;
        if (MODE == 0) {
            pA = (rA < ge) ? g_perm[rA] : -1;
            pB = (rB < ge) ? g_perm[rB] : -1;
        }
        #pragma unroll
        for (int ni = 0; ni < 4; ni++) {
            int col = nbase + wn + ni*8 + 2*tg;
            float c0 = acc[mi][ni][0], c1 = acc[mi][ni][1];
            float c2 = acc[mi][ni][2], c3 = acc[mi][ni][3];
            if (MODE == 0) {
                if (pA >= 0) *(float2*)&C[((size_t)pA << 9) + col] = make_float2(c0, c1);
                if (pB >= 0) *(float2*)&C[((size_t)pB << 9) + col] = make_float2(c2, c3);
            } else if (MODE == 1) {
                float2 bb = *(const float2*)&bias[col];
                float s0 = 1.f/(1.f + __expf(-(c0 + bb.x)));
                float s1 = 1.f/(1.f + __expf(-(c1 + bb.y)));
                float s2 = 1.f/(1.f + __expf(-(c2 + bb.x)));
                float s3 = 1.f/(1.f + __expf(-(c3 + bb.y)));
                *(float2*)&C[((size_t)pA << 9) + col] = make_float2(s0, s1);
                *(float2*)&C[((size_t)pB << 9) + col] = make_float2(s2, s3);
            } else if (MODE == 2) {
                float2 bb = *(const float2*)&bias[col];
                size_t oA = ((size_t)pA << 9) + col, oB = ((size_t)pB << 9) + col;
                float2 zA = *(const float2*)&g_z[oA], zB = *(const float2*)&g_z[oB];
                float2 nA = *(const float2*)&A_[oA], nB = *(const float2*)&A_[oB];
                float h0 = tanhf(c0 + bb.x), h1 = tanhf(c1 + bb.y);
                float h2 = tanhf(c2 + bb.x), h3 = tanhf(c3 + bb.y);
                *(float2*)&C[oA] = make_float2((1.f-zA.x)*nA.x + zA.x*h0,
                                               (1.f-zA.y)*nA.y + zA.y*h1);
                *(float2*)&C[oB] = make_float2((1.f-zB.x)*nB.x + zB.x*h2,
                                               (1.f-zB.y)*nB.y + zB.y*h3);
            } else { // MODE 3
                *(float2*)&C[((size_t)pA << 9) + col] = make_float2(c0, c1);
                *(float2*)&C[((size_t)pB << 9) + col] = make_float2(c2, c3);
            }
        }
    }
}

// ---------------- launch --------------------------------------------------------
extern "C" void kernel_launch(void* const* d_in, const int* in_sizes, int n_in,
                              void* d_out, int out_size)
{
    const float* nodes  = (const float*)d_in[0];
    const int*   mask   = (const int*)  d_in[1];
    const int*   ntw    = (const int*)  d_in[2];
    const float* W_in   = (const float*)d_in[3];
    const float* W_out  = (const float*)d_in[4];
    const float* a_in_q = (const float*)d_in[5];
    const float* a_in_v = (const float*)d_in[6];
    const float* a_out_q= (const float*)d_in[7];
    const float* a_out_v= (const float*)d_in[8];
    const float* W_r    = (const float*)d_in[9];
    const float* b_r    = (const float*)d_in[10];
    const float* W_z    = (const float*)d_in[11];
    const float* b_z    = (const float*)d_in[12];
    const float* W_t    = (const float*)d_in[13];
    const float* b_t    = (const float*)d_in[14];
    float* out = (float*)d_out;

    k_prep<<<1, 1024>>>(ntw);
    k_zero<<<4096, 256>>>();
    k_mma<0><<<dim3(4, 64, 3), 512>>>(nodes, W_in,  nullptr, nullptr, 0);
    k_mma<0><<<dim3(4, 64, 3), 512>>>(nodes, W_out, nullptr, nullptr, 1);
    k_dots<<<M_TOT, 128>>>(nodes, a_in_q, a_in_v, a_out_q, a_out_v);
    k_p<<<dim3(M_TOT, 2), 256>>>(mask);
    k_mma<3><<<dim3(4, 8, 16), 512>>>(nullptr, nullptr, nullptr, nullptr, 0);
    k_mma<1><<<dim3(4, 64), 512>>>(nodes, W_r, b_r, nullptr, 0);
    k_mma<1><<<dim3(4, 64), 512>>>(nodes, W_z, b_z, nullptr, 1);
    k_mma<2><<<dim3(4, 64), 512>>>(nodes, W_t, b_t, out, 0);
}

// round 6
// speedup vs baseline: 3.6687x; 1.2540x over previous
#include <cuda_runtime.h>
#include <math.h>

#define M_TOT 8192
#define DD 512
#define WSZ (3*512*512)   // 786432 floats: size of every weight blob

// ---------------- scratch (static device globals) ----------------
__device__ int   g_perm[M_TOT];
__device__ int   g_group[4];
__device__ float g_ndr[M_TOT*DD];        // tf32-rounded nodes
__device__ float g_node_in [M_TOT*DD];   // tf32-rounded
__device__ float g_node_out[M_TOT*DD];   // tf32-rounded
__device__ float g_h_in [M_TOT*DD];      // tf32-rounded
__device__ float g_h_out[M_TOT*DD];      // tf32-rounded
__device__ float g_rn[M_TOT*DD];         // tf32-rounded r*nodes
__device__ float g_z[M_TOT*DD];          // full fp32
__device__ float g_w[5*WSZ];             // rounded W_in,W_out,W_r,W_z,W_t
__device__ float g_sq[2*M_TOT];
__device__ float g_sv[2*M_TOT];
__device__ float g_eq[2*M_TOT];
__device__ float g_fq[2*M_TOT];
__device__ float g_ev[2*M_TOT];
__device__ float g_fv[2*M_TOT];
__device__ float g_p[2*M_TOT*1024];      // tf32-rounded probs (64MB)

// ---------------- helpers ----------------
__device__ __forceinline__ float f2t(float x) {
    unsigned r;
    asm("cvt.rna.tf32.f32 %0, %1;" : "=r"(r) : "f"(x));
    return __uint_as_float(r);
}
__device__ __forceinline__ float4 cvt4(float4 v) {
    return make_float4(f2t(v.x), f2t(v.y), f2t(v.z), f2t(v.w));
}
__device__ __forceinline__ void mma8(float* c, const float* a, const float* b) {
    asm volatile(
        "mma.sync.aligned.m16n8k8.row.col.f32.tf32.tf32.f32 "
        "{%0,%1,%2,%3}, {%4,%5,%6,%7}, {%8,%9}, {%0,%1,%2,%3};\n"
        : "+f"(c[0]), "+f"(c[1]), "+f"(c[2]), "+f"(c[3])
        : "r"(__float_as_uint(a[0])), "r"(__float_as_uint(a[1])),
          "r"(__float_as_uint(a[2])), "r"(__float_as_uint(a[3])),
          "r"(__float_as_uint(b[0])), "r"(__float_as_uint(b[1])));
}
__device__ __forceinline__ void cpa16(unsigned dst, const float* src, bool v) {
    int sz = v ? 16 : 0;
    asm volatile("cp.async.cg.shared.global [%0], [%1], 16, %2;\n"
                 :: "r"(dst), "l"(src), "r"(sz));
}
__device__ __forceinline__ void cpa_commit() {
    asm volatile("cp.async.commit_group;\n");
}

// ---------------- prep: dtype-detect node_type, counting sort ----------
__global__ void k_prep(const int* __restrict__ ntw)
{
    __shared__ int s_flag;
    __shared__ int s_cnt[1024*3];
    __shared__ int s_tot[3];
    int tid = threadIdx.x;
    if (tid == 0) s_flag = 0;
    __syncthreads();
    int bad = 0;
    for (int i = tid; i < 4096; i += 1024)
        if (ntw[2*i+1] != 0) bad = 1;
    if (bad) atomicOr(&s_flag, 1);
    __syncthreads();
    int is64 = (s_flag == 0);

    int tv[8];
    int c0 = 0, c1 = 0, c2 = 0;
    for (int k = 0; k < 8; k++) {
        int idx = tid*8 + k;
        int v = is64 ? ntw[2*idx] : ntw[idx];
        int t = (v >= 2 && v <= 4) ? (v - 2) : -1;
        tv[k] = t;
        if (t == 0) c0++; else if (t == 1) c1++; else if (t == 2) c2++;
    }
    s_cnt[tid*3+0] = c0; s_cnt[tid*3+1] = c1; s_cnt[tid*3+2] = c2;
    __syncthreads();
    if (tid < 3) {
        int run = 0;
        for (int i = 0; i < 1024; i++) {
            int c = s_cnt[i*3+tid]; s_cnt[i*3+tid] = run; run += c;
        }
        s_tot[tid] = run;
    }
    __syncthreads();
    if (tid == 0) {
        g_group[0] = 0;
        g_group[1] = s_tot[0];
        g_group[2] = s_tot[0] + s_tot[1];
        g_group[3] = s_tot[0] + s_tot[1] + s_tot[2];
    }
    int b0 = s_cnt[tid*3+0];
    int b1 = s_tot[0] + s_cnt[tid*3+1];
    int b2 = s_tot[0] + s_tot[1] + s_cnt[tid*3+2];
    for (int k = 0; k < 8; k++) {
        int idx = tid*8 + k;
        int t = tv[k];
        if (t == 0)      g_perm[b0++] = idx;
        else if (t == 1) g_perm[b1++] = idx;
        else if (t == 2) g_perm[b2++] = idx;
    }
}

__global__ void k_zero()
{
    size_t i = (size_t)blockIdx.x * blockDim.x + threadIdx.x;
    float4 zz = make_float4(0.f, 0.f, 0.f, 0.f);
    ((float4*)g_node_in)[i]  = zz;
    ((float4*)g_node_out)[i] = zz;
}

// ---------------- round nodes + 5 weight blobs to tf32 -------------------------
struct CvtSrcs { const float* nodes; const float* w0; const float* w1;
                 const float* w2; const float* w3; const float* w4; };
__global__ void k_cvt_all(CvtSrcs s)
{
    int i = blockIdx.x * blockDim.x + threadIdx.x;   // float4 index
    const int NF4 = M_TOT*DD/4;        // 1048576
    const int WF4 = WSZ/4;             // 196608
    if (i < NF4) {
        ((float4*)g_ndr)[i] = cvt4(((const float4*)s.nodes)[i]);
    } else {
        int j = i - NF4;
        int wi = j / WF4, off = j % WF4;
        const float* src = (wi==0)?s.w0:(wi==1)?s.w1:(wi==2)?s.w2:(wi==3)?s.w3:s.w4;
        ((float4*)(g_w + (size_t)wi*WSZ))[off] = cvt4(((const float4*)src)[off]);
    }
}

// ---------------- per-row dots + factored exps ------------------------
__device__ __forceinline__ float dot4(float4 a, float4 b) {
    return a.x*b.x + a.y*b.y + a.z*b.z + a.w*b.w;
}
__global__ void k_dots(const float* __restrict__ nodes,
    const float* __restrict__ aqi, const float* __restrict__ avi,
    const float* __restrict__ aqo, const float* __restrict__ avo)
{
    int row = blockIdx.x, tid = threadIdx.x;
    size_t off = ((size_t)row << 9) + tid*4;
    int d = tid*4;
    float4 nv = *(const float4*)(nodes + off);
    float4 ni = *(const float4*)(g_node_in + off);
    float4 no = *(const float4*)(g_node_out + off);
    float s0 = dot4(nv, *(const float4*)(aqi + d));
    float s1 = dot4(ni, *(const float4*)(avi + d));
    float s2 = dot4(nv, *(const float4*)(aqo + d));
    float s3 = dot4(no, *(const float4*)(avo + d));
    #pragma unroll
    for (int o2 = 16; o2; o2 >>= 1) {
        s0 += __shfl_down_sync(0xffffffffu, s0, o2);
        s1 += __shfl_down_sync(0xffffffffu, s1, o2);
        s2 += __shfl_down_sync(0xffffffffu, s2, o2);
        s3 += __shfl_down_sync(0xffffffffu, s3, o2);
    }
    __shared__ float sm[4][4];
    int w = tid >> 5, l = tid & 31;
    if (l == 0) { sm[w][0]=s0; sm[w][1]=s1; sm[w][2]=s2; sm[w][3]=s3; }
    __syncthreads();
    if (tid == 0) {
        float r0=0,r1=0,r2=0,r3=0;
        #pragma unroll
        for (int i = 0; i < 4; i++) { r0+=sm[i][0]; r1+=sm[i][1]; r2+=sm[i][2]; r3+=sm[i][3]; }
        g_sq[row] = r0; g_sv[row] = r1;
        g_sq[M_TOT+row] = r2; g_sv[M_TOT+row] = r3;
        g_eq[row] = __expf(r0);        g_fq[row] = __expf(0.2f*r0);
        g_ev[row] = __expf(r1);        g_fv[row] = __expf(0.2f*r1);
        g_eq[M_TOT+row] = __expf(r2);  g_fq[M_TOT+row] = __expf(0.2f*r2);
        g_ev[M_TOT+row] = __expf(r3);  g_fv[M_TOT+row] = __expf(0.2f*r3);
    }
}

// ---------------- P: normalized attention probabilities (tf32-rounded) ----------
__global__ __launch_bounds__(256) void k_p(const int* __restrict__ mask)
{
    int row = blockIdx.x, dir = blockIdx.y;
    int b = row >> 10;
    int tid = threadIdx.x;
    size_t base = ((size_t)(dir*M_TOT + row)) << 10;
    int gi = dir*M_TOT + row;
    float sq = g_sq[gi], Eq = g_eq[gi], Fq = g_fq[gi];
    int jb = dir*M_TOT + (b << 10);
    int4   mv = ((const int4*)(mask + base))[tid];
    float4 sv = ((const float4*)(g_sv + jb))[tid];
    float4 ev = ((const float4*)(g_ev + jb))[tid];
    float4 fv = ((const float4*)(g_fv + jb))[tid];
    float w0 = (mv.x > 0) ? ((sq + sv.x >= 0.f) ? Eq*ev.x : Fq*fv.x) : 0.f;
    float w1 = (mv.y > 0) ? ((sq + sv.y >= 0.f) ? Eq*ev.y : Fq*fv.y) : 0.f;
    float w2 = (mv.z > 0) ? ((sq + sv.z >= 0.f) ? Eq*ev.z : Fq*fv.z) : 0.f;
    float w3 = (mv.w > 0) ? ((sq + sv.w >= 0.f) ? Eq*ev.w : Fq*fv.w) : 0.f;
    float s = w0 + w1 + w2 + w3;
    #pragma unroll
    for (int o = 16; o; o >>= 1) s += __shfl_xor_sync(0xffffffffu, s, o);
    __shared__ float swarp[8];
    __shared__ float sinv;
    if ((tid & 31) == 0) swarp[tid >> 5] = s;
    __syncthreads();
    if (tid < 8) {
        float v = swarp[tid];
        #pragma unroll
        for (int o = 4; o; o >>= 1) v += __shfl_xor_sync(0xffu, v, o);
        if (tid == 0) sinv = 1.f / v;
    }
    __syncthreads();
    float inv = sinv;
    ((float4*)(g_p + base))[tid] =
        make_float4(f2t(w0*inv), f2t(w1*inv), f2t(w2*inv), f2t(w3*inv));
}

// ---------------- tf32 MMA GEMM, 3-stage cp.async pipeline ----------------------
// MODE 0: typed linear. z = which*3 + t. A = g_ndr gathered via perm, K=512.
//         C = node_in/node_out (tf32-rounded, scattered via perm).
// MODE 1: gates. z=0 -> r: g_rn = tf32(sigmoid(.)*nodes); z=1 -> g_z = sigmoid(.)
//         A = [h_in|h_out|ndr], K=1536.
// MODE 2: final: out = (1-z)*nodes + z*tanh(.). A = [h_in|h_out|rn], K=1536.
// MODE 3: GAT: h = P @ V per (dir,batch). K=1024. C = h (tf32-rounded).
#define STG_F (128*36 + 32*136)     // 8960 floats per stage
#define SMEM_BYTES (3*STG_F*4)      // 107520 B

template<int MODE>
__global__ __launch_bounds__(512) void k_mma(
    const float* __restrict__ nodes_raw,
    const float* __restrict__ bias_a, const float* __restrict__ bias_b,
    float* __restrict__ Cout)
{
    constexpr int KIT = (MODE==0) ? 16 : (MODE==3) ? 32 : 48;
    extern __shared__ float smem[];
    unsigned sbase = (unsigned)__cvta_generic_to_shared(smem);

    int tid = threadIdx.x;
    int nbase = blockIdx.x * 128;
    int am = tid >> 3, kq = tid & 7;      // A staging: rows am, am+64
    int bk = tid >> 5, bnq = tid & 31;    // B staging: k rows bk, bk+16

    int zed = blockIdx.z;
    int mbase = blockIdx.y * 128;
    int ge = 1 << 30;
    const float* Bp = nullptr;
    float* C = Cout;
    const float *pa0 = nullptr, *pa1 = nullptr;          // MODE 0/3 row ptrs
    const float *sA0 = nullptr, *sA1 = nullptr, *sA2 = nullptr; // concat seg bases (row am)

    if (MODE == 0) {
        int t = zed % 3, which = zed / 3;
        int gs = g_group[t]; ge = g_group[t+1];
        mbase = gs + blockIdx.y * 128;
        if (mbase >= ge) return;
        Bp = g_w + (size_t)which*WSZ + (size_t)t*DD*DD;
        C = which ? g_node_out : g_node_in;
        int r0 = mbase + am, r1 = r0 + 64;
        pa0 = (r0 < ge) ? g_ndr + ((size_t)g_perm[r0] << 9) : nullptr;
        pa1 = (r1 < ge) ? g_ndr + ((size_t)g_perm[r1] << 9) : nullptr;
    } else if (MODE == 1 || MODE == 2) {
        size_t o0 = (size_t)(mbase + am) << 9;
        sA0 = g_h_in + o0;
        sA1 = g_h_out + o0;
        sA2 = (MODE == 1 ? g_ndr : g_rn) + o0;
        Bp = g_w + (size_t)((MODE == 1) ? (2 + zed) : 4) * WSZ;
    } else { // MODE 3
        int dir = zed >> 3, b = zed & 7;
        pa0 = g_p + ((size_t)(dir*M_TOT + (b << 10) + mbase + am) << 10);
        pa1 = pa0 + ((size_t)64 << 10);
        Bp = (dir ? g_node_out : g_node_in) + (((size_t)(b << 10)) << 9);
        C  = (dir ? g_h_out  : g_h_in) + (((size_t)(b << 10)) << 9);
    }

    auto issue = [&](int kt) {
        unsigned s = (unsigned)((kt % 3) * STG_F);
        unsigned dA0 = sbase + (s + am*36 + kq*4) * 4;
        unsigned dA1 = dA0 + 64*36*4;
        int col = kt*32 + kq*4;
        if (MODE == 0) {
            cpa16(dA0, pa0 ? pa0 + col : g_ndr, pa0 != nullptr);
            cpa16(dA1, pa1 ? pa1 + col : g_ndr, pa1 != nullptr);
        } else if (MODE == 3) {
            cpa16(dA0, pa0 + col, true);
            cpa16(dA1, pa1 + col, true);
        } else {
            int seg = kt >> 4;
            int off = (kt & 15)*32 + kq*4;
            const float* sb = (seg == 0) ? sA0 : (seg == 1) ? sA1 : sA2;
            cpa16(dA0, sb + off, true);
            cpa16(dA1, sb + off + (64 << 9), true);
        }
        unsigned dB0 = sbase + (s + 128*36 + bk*136 + bnq*4) * 4;
        unsigned dB1 = dB0 + 16*136*4;
        const float* sB = Bp + (size_t)(kt*32 + bk)*DD + nbase + bnq*4;
        cpa16(dB0, sB, true);
        cpa16(dB1, sB + (size_t)16*DD, true);
    };

    // fragment ids
    int lane = tid & 31, g = lane >> 2, tg = lane & 3;
    int wid = tid >> 5;
    int wm = (wid >> 2) * 32, wn = (wid & 3) * 32;

    float acc[2][4][4];
    #pragma unroll
    for (int mi = 0; mi < 2; mi++)
        #pragma unroll
        for (int ni = 0; ni < 4; ni++)
            #pragma unroll
            for (int q = 0; q < 4; q++) acc[mi][ni][q] = 0.f;

    issue(0); cpa_commit();
    issue(1); cpa_commit();

    for (int kt = 0; kt < KIT; kt++) {
        asm volatile("cp.async.wait_group 1;\n");
        __syncthreads();
        if (kt + 2 < KIT) issue(kt + 2);
        cpa_commit();

        const float* As = smem + (kt % 3) * STG_F;
        const float* Bs = As + 128*36;
        #pragma unroll
        for (int ks = 0; ks < 4; ks++) {
            int k0 = ks*8;
            float a[2][4], bf[4][2];
            #pragma unroll
            for (int mi = 0; mi < 2; mi++) {
                int mr = wm + mi*16 + g;
                a[mi][0] = As[mr*36     + k0 + tg];
                a[mi][1] = As[(mr+8)*36 + k0 + tg];
                a[mi][2] = As[mr*36     + k0 + tg + 4];
                a[mi][3] = As[(mr+8)*36 + k0 + tg + 4];
            }
            #pragma unroll
            for (int ni = 0; ni < 4; ni++) {
                bf[ni][0] = Bs[(k0+tg)*136   + wn + ni*8 + g];
                bf[ni][1] = Bs[(k0+tg+4)*136 + wn + ni*8 + g];
            }
            #pragma unroll
            for (int mi = 0; mi < 2; mi++)
                #pragma unroll
                for (int ni = 0; ni < 4; ni++)
                    mma8(acc[mi][ni], a[mi], bf[ni]);
        }
    }

    // ---- epilogue
    #pragma unroll
    for (int mi = 0; mi < 2; mi++) {
        int rA = mbase + wm + mi*16 + g;
        int rB = rA + 8;
        int pA = rA, pB = rB;
        if (MODE == 0) {
            pA = (rA < ge) ? g_perm[rA] : -1;
            pB = (rB < ge) ? g_perm[rB] : -1;
        }
        #pragma unroll
        for (int ni = 0; ni < 4; ni++) {
            int col = nbase + wn + ni*8 + 2*tg;
            float c0 = acc[mi][ni][0], c1 = acc[mi][ni][1];
            float c2 = acc[mi][ni][2], c3 = acc[mi][ni][3];
            if (MODE == 0) {
                if (pA >= 0) *(float2*)&C[((size_t)pA << 9) + col] =
                    make_float2(f2t(c0), f2t(c1));
                if (pB >= 0) *(float2*)&C[((size_t)pB << 9) + col] =
                    make_float2(f2t(c2), f2t(c3));
            } else if (MODE == 1) {
                size_t oA = ((size_t)pA << 9) + col, oB = ((size_t)pB << 9) + col;
                if (zed == 0) {
                    float2 bb = *(const float2*)&bias_a[col];
                    float2 nA = *(const float2*)&nodes_raw[oA];
                    float2 nB = *(const float2*)&nodes_raw[oB];
                    float s0 = 1.f/(1.f + __expf(-(c0 + bb.x)));
                    float s1 = 1.f/(1.f + __expf(-(c1 + bb.y)));
                    float s2 = 1.f/(1.f + __expf(-(c2 + bb.x)));
                    float s3 = 1.f/(1.f + __expf(-(c3 + bb.y)));
                    *(float2*)&g_rn[oA] = make_float2(f2t(s0*nA.x), f2t(s1*nA.y));
                    *(float2*)&g_rn[oB] = make_float2(f2t(s2*nB.x), f2t(s3*nB.y));
                } else {
                    float2 bb = *(const float2*)&bias_b[col];
                    float s0 = 1.f/(1.f + __expf(-(c0 + bb.x)));
                    float s1 = 1.f/(1.f + __expf(-(c1 + bb.y)));
                    float s2 = 1.f/(1.f + __expf(-(c2 + bb.x)));
                    float s3 = 1.f/(1.f + __expf(-(c3 + bb.y)));
                    *(float2*)&g_z[oA] = make_float2(s0, s1);
                    *(float2*)&g_z[oB] = make_float2(s2, s3);
                }
            } else if (MODE == 2) {
                float2 bb = *(const float2*)&bias_a[col];
                size_t oA = ((size_t)pA << 9) + col, oB = ((size_t)pB << 9) + col;
                float2 zA = *(const float2*)&g_z[oA], zB = *(const float2*)&g_z[oB];
                float2 nA = *(const float2*)&nodes_raw[oA], nB = *(const float2*)&nodes_raw[oB];
                float h0 = tanhf(c0 + bb.x), h1 = tanhf(c1 + bb.y);
                float h2 = tanhf(c2 + bb.x), h3 = tanhf(c3 + bb.y);
                *(float2*)&C[oA] = make_float2((1.f-zA.x)*nA.x + zA.x*h0,
                                               (1.f-zA.y)*nA.y + zA.y*h1);
                *(float2*)&C[oB] = make_float2((1.f-zB.x)*nB.x + zB.x*h2,
                                               (1.f-zB.y)*nB.y + zB.y*h3);
            } else { // MODE 3
                *(float2*)&C[((size_t)pA << 9) + col] = make_float2(f2t(c0), f2t(c1));
                *(float2*)&C[((size_t)pB << 9) + col] = make_float2(f2t(c2), f2t(c3));
            }
        }
    }
}

// ---------------- launch --------------------------------------------------------
extern "C" void kernel_launch(void* const* d_in, const int* in_sizes, int n_in,
                              void* d_out, int out_size)
{
    const float* nodes  = (const float*)d_in[0];
    const int*   mask   = (const int*)  d_in[1];
    const int*   ntw    = (const int*)  d_in[2];
    const float* W_in   = (const float*)d_in[3];
    const float* W_out  = (const float*)d_in[4];
    const float* a_in_q = (const float*)d_in[5];
    const float* a_in_v = (const float*)d_in[6];
    const float* a_out_q= (const float*)d_in[7];
    const float* a_out_v= (const float*)d_in[8];
    const float* W_r    = (const float*)d_in[9];
    const float* b_r    = (const float*)d_in[10];
    const float* W_z    = (const float*)d_in[11];
    const float* b_z    = (const float*)d_in[12];
    const float* W_t    = (const float*)d_in[13];
    const float* b_t    = (const float*)d_in[14];
    float* out = (float*)d_out;

    cudaFuncSetAttribute(k_mma<0>, cudaFuncAttributeMaxDynamicSharedMemorySize, SMEM_BYTES);
    cudaFuncSetAttribute(k_mma<1>, cudaFuncAttributeMaxDynamicSharedMemorySize, SMEM_BYTES);
    cudaFuncSetAttribute(k_mma<2>, cudaFuncAttributeMaxDynamicSharedMemorySize, SMEM_BYTES);
    cudaFuncSetAttribute(k_mma<3>, cudaFuncAttributeMaxDynamicSharedMemorySize, SMEM_BYTES);

    k_prep<<<1, 1024>>>(ntw);
    k_zero<<<4096, 256>>>();
    CvtSrcs cs = { nodes, W_in, W_out, W_r, W_z, W_t };
    k_cvt_all<<<7936, 256>>>(cs);
    k_mma<0><<<dim3(4, 64, 6), 512, SMEM_BYTES>>>(nodes, nullptr, nullptr, nullptr);
    k_dots<<<M_TOT, 128>>>(nodes, a_in_q, a_in_v, a_out_q, a_out_v);
    k_p<<<dim3(M_TOT, 2), 256>>>(mask);
    k_mma<3><<<dim3(4, 8, 16), 512, SMEM_BYTES>>>(nodes, nullptr, nullptr, nullptr);
    k_mma<1><<<dim3(4, 64, 2), 512, SMEM_BYTES>>>(nodes, b_r, b_z, nullptr);
    k_mma<2><<<dim3(4, 64, 1), 512, SMEM_BYTES>>>(nodes, b_t, nullptr, out);
}

// round 7
// speedup vs baseline: 6.7511x; 1.8402x over previous
#include <cuda_runtime.h>
#include <cuda_bf16.h>
#include <math.h>

#define M_TOT 8192
#define DD 512
#define WSZ (3*512*512)   // elements per weight blob

typedef __nv_bfloat16 bf16;

// ---------------- scratch ----------------
__device__ int   g_perm[M_TOT];
__device__ int   g_group[4];
__device__ bf16  g_ndr[M_TOT*DD];        // bf16 nodes
__device__ bf16  g_node_in [M_TOT*DD];
__device__ bf16  g_node_out[M_TOT*DD];
__device__ bf16  g_h_in [M_TOT*DD];
__device__ bf16  g_h_out[M_TOT*DD];
__device__ bf16  g_rn[M_TOT*DD];         // bf16 r*nodes
__device__ float g_z[M_TOT*DD];          // fp32
__device__ bf16  g_w[5*WSZ];             // bf16 W_in,W_out,W_r,W_z,W_t
__device__ bf16  g_p[2*M_TOT*1024];      // bf16 probs (32MB)
__device__ float g_sq[2*M_TOT];
__device__ float g_sv[2*M_TOT];
__device__ float g_eq[2*M_TOT];
__device__ float g_fq[2*M_TOT];
__device__ float g_ev[2*M_TOT];
__device__ float g_fv[2*M_TOT];

// ---------------- helpers ----------------
__device__ __forceinline__ unsigned pk(float a, float b) {
    __nv_bfloat162 t = __floats2bfloat162_rn(a, b);
    return *(unsigned*)&t;
}
__device__ __forceinline__ void mma16(float* c, const unsigned* a, unsigned b0, unsigned b1) {
    asm volatile(
        "mma.sync.aligned.m16n8k16.row.col.f32.bf16.bf16.f32 "
        "{%0,%1,%2,%3}, {%4,%5,%6,%7}, {%8,%9}, {%0,%1,%2,%3};\n"
        : "+f"(c[0]), "+f"(c[1]), "+f"(c[2]), "+f"(c[3])
        : "r"(a[0]), "r"(a[1]), "r"(a[2]), "r"(a[3]), "r"(b0), "r"(b1));
}
__device__ __forceinline__ void ldsm4(unsigned* r, unsigned addr) {
    asm volatile("ldmatrix.sync.aligned.m8n8.x4.shared.b16 {%0,%1,%2,%3}, [%4];"
        : "=r"(r[0]), "=r"(r[1]), "=r"(r[2]), "=r"(r[3]) : "r"(addr));
}
__device__ __forceinline__ void ldsm4t(unsigned* r, unsigned addr) {
    asm volatile("ldmatrix.sync.aligned.m8n8.x4.trans.shared.b16 {%0,%1,%2,%3}, [%4];"
        : "=r"(r[0]), "=r"(r[1]), "=r"(r[2]), "=r"(r[3]) : "r"(addr));
}
__device__ __forceinline__ void cpa16(unsigned dst, const void* src, bool v) {
    int sz = v ? 16 : 0;
    asm volatile("cp.async.cg.shared.global [%0], [%1], 16, %2;\n"
                 :: "r"(dst), "l"(src), "r"(sz));
}
__device__ __forceinline__ void cpa_commit() {
    asm volatile("cp.async.commit_group;\n");
}

// ---------------- prep ----------------
__global__ void k_prep(const int* __restrict__ ntw)
{
    __shared__ int s_flag;
    __shared__ int s_cnt[1024*3];
    __shared__ int s_tot[3];
    int tid = threadIdx.x;
    if (tid == 0) s_flag = 0;
    __syncthreads();
    int bad = 0;
    for (int i = tid; i < 4096; i += 1024)
        if (ntw[2*i+1] != 0) bad = 1;
    if (bad) atomicOr(&s_flag, 1);
    __syncthreads();
    int is64 = (s_flag == 0);

    int tv[8];
    int c0 = 0, c1 = 0, c2 = 0;
    for (int k = 0; k < 8; k++) {
        int idx = tid*8 + k;
        int v = is64 ? ntw[2*idx] : ntw[idx];
        int t = (v >= 2 && v <= 4) ? (v - 2) : -1;
        tv[k] = t;
        if (t == 0) c0++; else if (t == 1) c1++; else if (t == 2) c2++;
    }
    s_cnt[tid*3+0] = c0; s_cnt[tid*3+1] = c1; s_cnt[tid*3+2] = c2;
    __syncthreads();
    if (tid < 3) {
        int run = 0;
        for (int i = 0; i < 1024; i++) {
            int c = s_cnt[i*3+tid]; s_cnt[i*3+tid] = run; run += c;
        }
        s_tot[tid] = run;
    }
    __syncthreads();
    if (tid == 0) {
        g_group[0] = 0;
        g_group[1] = s_tot[0];
        g_group[2] = s_tot[0] + s_tot[1];
        g_group[3] = s_tot[0] + s_tot[1] + s_tot[2];
    }
    int b0 = s_cnt[tid*3+0];
    int b1 = s_tot[0] + s_cnt[tid*3+1];
    int b2 = s_tot[0] + s_tot[1] + s_cnt[tid*3+2];
    for (int k = 0; k < 8; k++) {
        int idx = tid*8 + k;
        int t = tv[k];
        if (t == 0)      g_perm[b0++] = idx;
        else if (t == 1) g_perm[b1++] = idx;
        else if (t == 2) g_perm[b2++] = idx;
    }
}

__global__ void k_zero()   // zero bf16 node_in/out (8MB each)
{
    int i = blockIdx.x * blockDim.x + threadIdx.x;   // 0..524287 float4
    float4 zz = make_float4(0.f, 0.f, 0.f, 0.f);
    ((float4*)g_node_in)[i]  = zz;
    ((float4*)g_node_out)[i] = zz;
}

// ---------------- convert nodes + 5 weight blobs to bf16 ----------------
struct CvtSrcs { const float* nodes; const float* w0; const float* w1;
                 const float* w2; const float* w3; const float* w4; };
__global__ void k_cvt_all(CvtSrcs s)
{
    int i = blockIdx.x * blockDim.x + threadIdx.x;   // float4 index
    const int NF4 = M_TOT*DD/4;        // 1048576
    const int WF4 = WSZ/4;             // 196608
    if (i < NF4) {
        float4 v = ((const float4*)s.nodes)[i];
        ((uint2*)g_ndr)[i] = make_uint2(pk(v.x, v.y), pk(v.z, v.w));
    } else {
        int j = i - NF4;
        int wi = j / WF4, off = j % WF4;
        const float* src = (wi==0)?s.w0:(wi==1)?s.w1:(wi==2)?s.w2:(wi==3)?s.w3:s.w4;
        float4 v = ((const float4*)src)[off];
        ((uint2*)g_w)[j] = make_uint2(pk(v.x, v.y), pk(v.z, v.w));
    }
}

// ---------------- per-row dots + factored exps ----------------
__device__ __forceinline__ float dot4(float4 a, float4 b) {
    return a.x*b.x + a.y*b.y + a.z*b.z + a.w*b.w;
}
__device__ __forceinline__ float dotb(uint2 u, float4 b) {
    float2 f0 = __bfloat1622float2(*(__nv_bfloat162*)&u.x);
    float2 f1 = __bfloat1622float2(*(__nv_bfloat162*)&u.y);
    return f0.x*b.x + f0.y*b.y + f1.x*b.z + f1.y*b.w;
}
__global__ void k_dots(const float* __restrict__ nodes,
    const float* __restrict__ aqi, const float* __restrict__ avi,
    const float* __restrict__ aqo, const float* __restrict__ avo)
{
    int row = blockIdx.x, tid = threadIdx.x;
    size_t off = ((size_t)row << 9) + tid*4;
    int d = tid*4;
    float4 nv = *(const float4*)(nodes + off);
    uint2 ni = *(const uint2*)(g_node_in + off);
    uint2 no = *(const uint2*)(g_node_out + off);
    float s0 = dot4(nv, *(const float4*)(aqi + d));
    float s1 = dotb(ni, *(const float4*)(avi + d));
    float s2 = dot4(nv, *(const float4*)(aqo + d));
    float s3 = dotb(no, *(const float4*)(avo + d));
    #pragma unroll
    for (int o2 = 16; o2; o2 >>= 1) {
        s0 += __shfl_down_sync(0xffffffffu, s0, o2);
        s1 += __shfl_down_sync(0xffffffffu, s1, o2);
        s2 += __shfl_down_sync(0xffffffffu, s2, o2);
        s3 += __shfl_down_sync(0xffffffffu, s3, o2);
    }
    __shared__ float sm[4][4];
    int w = tid >> 5, l = tid & 31;
    if (l == 0) { sm[w][0]=s0; sm[w][1]=s1; sm[w][2]=s2; sm[w][3]=s3; }
    __syncthreads();
    if (tid == 0) {
        float r0=0,r1=0,r2=0,r3=0;
        #pragma unroll
        for (int i = 0; i < 4; i++) { r0+=sm[i][0]; r1+=sm[i][1]; r2+=sm[i][2]; r3+=sm[i][3]; }
        g_sq[row] = r0; g_sv[row] = r1;
        g_sq[M_TOT+row] = r2; g_sv[M_TOT+row] = r3;
        g_eq[row] = __expf(r0);        g_fq[row] = __expf(0.2f*r0);
        g_ev[row] = __expf(r1);        g_fv[row] = __expf(0.2f*r1);
        g_eq[M_TOT+row] = __expf(r2);  g_fq[M_TOT+row] = __expf(0.2f*r2);
        g_ev[M_TOT+row] = __expf(r3);  g_fv[M_TOT+row] = __expf(0.2f*r3);
    }
}

// ---------------- P: normalized attention probabilities (bf16) ----------------
__global__ __launch_bounds__(256) void k_p(const int* __restrict__ mask)
{
    int row = blockIdx.x, dir = blockIdx.y;
    int b = row >> 10;
    int tid = threadIdx.x;
    size_t base = ((size_t)(dir*M_TOT + row)) << 10;
    int gi = dir*M_TOT + row;
    float sq = g_sq[gi], Eq = g_eq[gi], Fq = g_fq[gi];
    int jb = dir*M_TOT + (b << 10);
    int4   mv = ((const int4*)(mask + base))[tid];
    float4 sv = ((const float4*)(g_sv + jb))[tid];
    float4 ev = ((const float4*)(g_ev + jb))[tid];
    float4 fv = ((const float4*)(g_fv + jb))[tid];
    float w0 = (mv.x > 0) ? ((sq + sv.x >= 0.f) ? Eq*ev.x : Fq*fv.x) : 0.f;
    float w1 = (mv.y > 0) ? ((sq + sv.y >= 0.f) ? Eq*ev.y : Fq*fv.y) : 0.f;
    float w2 = (mv.z > 0) ? ((sq + sv.z >= 0.f) ? Eq*ev.z : Fq*fv.z) : 0.f;
    float w3 = (mv.w > 0) ? ((sq + sv.w >= 0.f) ? Eq*ev.w : Fq*fv.w) : 0.f;
    float s = w0 + w1 + w2 + w3;
    #pragma unroll
    for (int o = 16; o; o >>= 1) s += __shfl_xor_sync(0xffffffffu, s, o);
    __shared__ float swarp[8];
    __shared__ float sinv;
    if ((tid & 31) == 0) swarp[tid >> 5] = s;
    __syncthreads();
    if (tid < 8) {
        float v = swarp[tid];
        #pragma unroll
        for (int o = 4; o; o >>= 1) v += __shfl_xor_sync(0xffu, v, o);
        if (tid == 0) sinv = 1.f / v;
    }
    __syncthreads();
    float inv = sinv;
    ((uint2*)g_p)[(base >> 2) + tid] =
        make_uint2(pk(w0*inv, w1*inv), pk(w2*inv, w3*inv));
}

// ---------------- bf16 MMA GEMM (m16n8k16 + ldmatrix + cp.async x3) -------------
// MODE 0: typed linear: z=which*3+t. A=g_ndr gathered via perm, K=512. C scattered.
// MODE 1: gates: z=0 -> g_rn = bf16(sigmoid(.)*nodes); z=1 -> g_z = sigmoid(.)
// MODE 2: final: out = (1-z)*nodes + z*tanh(.)
// MODE 3: GAT: h = P @ V per (dir,batch). K=1024.
#define APITCH 40
#define BPITCH 136
#define A_E (128*APITCH)       // 5120 bf16
#define B_E (32*BPITCH)        // 4352 bf16
#define STG_E (A_E + B_E)      // 9472 bf16 per stage
#define SMEM_BYTES (3*STG_E*2) // 56832 B

template<int MODE>
__global__ __launch_bounds__(512, 2) void k_mma(
    const float* __restrict__ nodes_raw,
    const float* __restrict__ bias_a, const float* __restrict__ bias_b,
    float* __restrict__ Cout)
{
    constexpr int KIT = (MODE==0) ? 16 : (MODE==3) ? 32 : 48;
    extern __shared__ bf16 smem[];
    unsigned sbase = (unsigned)__cvta_generic_to_shared(smem);

    int tid = threadIdx.x;
    int nbase = blockIdx.x * 128;
    int ar = tid >> 2, ac = tid & 3;      // A staging: row 0..127, 8-elt chunk 0..3
    int br = tid >> 4, bc = tid & 15;     // B staging: k-row 0..31, chunk 0..15

    int zed = blockIdx.z;
    int mbase = blockIdx.y * 128;
    int ge = 1 << 30;
    const bf16* Bp = nullptr;
    bf16* Cb = nullptr;
    const bf16 *pa = nullptr;                               // MODE 0/3
    const bf16 *sA0 = nullptr, *sA1 = nullptr, *sA2 = nullptr; // MODE 1/2 segs

    if (MODE == 0) {
        int t = zed % 3, which = zed / 3;
        int gs = g_group[t]; ge = g_group[t+1];
        mbase = gs + blockIdx.y * 128;
        if (mbase >= ge) return;
        Bp = g_w + (size_t)which*WSZ + (size_t)t*DD*DD;
        Cb = which ? g_node_out : g_node_in;
        int r0 = mbase + ar;
        pa = (r0 < ge) ? g_ndr + ((size_t)g_perm[r0] << 9) : nullptr;
    } else if (MODE == 1 || MODE == 2) {
        size_t o0 = (size_t)(mbase + ar) << 9;
        sA0 = g_h_in + o0;
        sA1 = g_h_out + o0;
        sA2 = (MODE == 1 ? g_ndr : g_rn) + o0;
        Bp = g_w + (size_t)((MODE == 1) ? (2 + zed) : 4) * WSZ;
    } else { // MODE 3
        int dir = zed >> 3, b = zed & 7;
        pa = g_p + ((size_t)(dir*M_TOT + (b << 10) + mbase + ar) << 10);
        Bp = (dir ? g_node_out : g_node_in) + (((size_t)(b << 10)) << 9);
        Cb = (dir ? g_h_out  : g_h_in) + (((size_t)(b << 10)) << 9);
    }

    auto issue = [&](int kt) {
        unsigned st = (unsigned)((kt % 3) * STG_E);
        unsigned dA = sbase + (st + ar*APITCH + ac*8) * 2;
        int col = kt*32 + ac*8;
        if (MODE == 0) {
            cpa16(dA, pa ? pa + col : (const bf16*)g_ndr, pa != nullptr);
        } else if (MODE == 3) {
            cpa16(dA, pa + col, true);
        } else {
            int seg = kt >> 4;
            int off = (kt & 15)*32 + ac*8;
            const bf16* sb = (seg == 0) ? sA0 : (seg == 1) ? sA1 : sA2;
            cpa16(dA, sb + off, true);
        }
        unsigned dB = sbase + (st + A_E + br*BPITCH + bc*8) * 2;
        cpa16(dB, Bp + (size_t)(kt*32 + br)*DD + nbase + bc*8, true);
    };

    // fragment lane decomposition
    int lane = tid & 31, wid = tid >> 5;
    int wm = (wid >> 2) * 32, wn = (wid & 3) * 32;
    int q = lane >> 3, li = lane & 7;
    int arow_f = li + (q & 1)*8;
    int acol_f = (q >> 1)*8;
    int g = lane >> 2, tg = lane & 3;

    float acc[2][4][4];
    #pragma unroll
    for (int mi = 0; mi < 2; mi++)
        #pragma unroll
        for (int ni = 0; ni < 4; ni++)
            #pragma unroll
            for (int qq = 0; qq < 4; qq++) acc[mi][ni][qq] = 0.f;

    issue(0); cpa_commit();
    issue(1); cpa_commit();

    for (int kt = 0; kt < KIT; kt++) {
        asm volatile("cp.async.wait_group 1;\n");
        __syncthreads();
        if (kt + 2 < KIT) issue(kt + 2);
        cpa_commit();

        unsigned As = sbase + (unsigned)((kt % 3) * STG_E) * 2;
        unsigned Bs = As + A_E * 2;
        #pragma unroll
        for (int ks = 0; ks < 32; ks += 16) {
            unsigned a[2][4], bfr[2][4];
            #pragma unroll
            for (int mi = 0; mi < 2; mi++)
                ldsm4(a[mi], As + ((wm + mi*16 + arow_f)*APITCH + ks + acol_f) * 2);
            #pragma unroll
            for (int n2 = 0; n2 < 2; n2++)
                ldsm4t(bfr[n2], Bs + ((ks + arow_f)*BPITCH + wn + n2*16 + acol_f) * 2);
            #pragma unroll
            for (int mi = 0; mi < 2; mi++)
                #pragma unroll
                for (int ni = 0; ni < 4; ni++)
                    mma16(acc[mi][ni], a[mi], bfr[ni>>1][(ni&1)*2], bfr[ni>>1][(ni&1)*2+1]);
        }
    }

    // ---- epilogue
    #pragma unroll
    for (int mi = 0; mi < 2; mi++) {
        int rA = mbase + wm + mi*16 + g;
        int rB = rA + 8;
        int pA = rA, pB = rB;
        if (MODE == 0) {
            pA = (rA < ge) ? g_perm[rA] : -1;
            pB = (rB < ge) ? g_perm[rB] : -1;
        }
        #pragma unroll
        for (int ni = 0; ni < 4; ni++) {
            int col = nbase + wn + ni*8 + 2*tg;
            float c0 = acc[mi][ni][0], c1 = acc[mi][ni][1];
            float c2 = acc[mi][ni][2], c3 = acc[mi][ni][3];
            if (MODE == 0) {
                if (pA >= 0) *(unsigned*)&Cb[((size_t)pA << 9) + col] = pk(c0, c1);
                if (pB >= 0) *(unsigned*)&Cb[((size_t)pB << 9) + col] = pk(c2, c3);
            } else if (MODE == 1) {
                size_t oA = ((size_t)pA << 9) + col, oB = ((size_t)pB << 9) + col;
                float2 bb = *(const float2*)&((zed == 0) ? bias_a : bias_b)[col];
                float s0 = 1.f/(1.f + __expf(-(c0 + bb.x)));
                float s1 = 1.f/(1.f + __expf(-(c1 + bb.y)));
                float s2 = 1.f/(1.f + __expf(-(c2 + bb.x)));
                float s3 = 1.f/(1.f + __expf(-(c3 + bb.y)));
                if (zed == 0) {
                    float2 nA = *(const float2*)&nodes_raw[oA];
                    float2 nB = *(const float2*)&nodes_raw[oB];
                    *(unsigned*)&g_rn[oA] = pk(s0*nA.x, s1*nA.y);
                    *(unsigned*)&g_rn[oB] = pk(s2*nB.x, s3*nB.y);
                } else {
                    *(float2*)&g_z[oA] = make_float2(s0, s1);
                    *(float2*)&g_z[oB] = make_float2(s2, s3);
                }
            } else if (MODE == 2) {
                float2 bb = *(const float2*)&bias_a[col];
                size_t oA = ((size_t)pA << 9) + col, oB = ((size_t)pB << 9) + col;
                float2 zA = *(const float2*)&g_z[oA], zB = *(const float2*)&g_z[oB];
                float2 nA = *(const float2*)&nodes_raw[oA], nB = *(const float2*)&nodes_raw[oB];
                float h0 = tanhf(c0 + bb.x), h1 = tanhf(c1 + bb.y);
                float h2 = tanhf(c2 + bb.x), h3 = tanhf(c3 + bb.y);
                *(float2*)&Cout[oA] = make_float2((1.f-zA.x)*nA.x + zA.x*h0,
                                                  (1.f-zA.y)*nA.y + zA.y*h1);
                *(float2*)&Cout[oB] = make_float2((1.f-zB.x)*nB.x + zB.x*h2,
                                                  (1.f-zB.y)*nB.y + zB.y*h3);
            } else { // MODE 3
                *(unsigned*)&Cb[((size_t)pA << 9) + col] = pk(c0, c1);
                *(unsigned*)&Cb[((size_t)pB << 9) + col] = pk(c2, c3);
            }
        }
    }
}

// ---------------- launch ----------------
extern "C" void kernel_launch(void* const* d_in, const int* in_sizes, int n_in,
                              void* d_out, int out_size)
{
    const float* nodes  = (const float*)d_in[0];
    const int*   mask   = (const int*)  d_in[1];
    const int*   ntw    = (const int*)  d_in[2];
    const float* W_in   = (const float*)d_in[3];
    const float* W_out  = (const float*)d_in[4];
    const float* a_in_q = (const float*)d_in[5];
    const float* a_in_v = (const float*)d_in[6];
    const float* a_out_q= (const float*)d_in[7];
    const float* a_out_v= (const float*)d_in[8];
    const float* W_r    = (const float*)d_in[9];
    const float* b_r    = (const float*)d_in[10];
    const float* W_z    = (const float*)d_in[11];
    const float* b_z    = (const float*)d_in[12];
    const float* W_t    = (const float*)d_in[13];
    const float* b_t    = (const float*)d_in[14];
    float* out = (float*)d_out;

    cudaFuncSetAttribute(k_mma<0>, cudaFuncAttributeMaxDynamicSharedMemorySize, SMEM_BYTES);
    cudaFuncSetAttribute(k_mma<1>, cudaFuncAttributeMaxDynamicSharedMemorySize, SMEM_BYTES);
    cudaFuncSetAttribute(k_mma<2>, cudaFuncAttributeMaxDynamicSharedMemorySize, SMEM_BYTES);
    cudaFuncSetAttribute(k_mma<3>, cudaFuncAttributeMaxDynamicSharedMemorySize, SMEM_BYTES);

    k_prep<<<1, 1024>>>(ntw);
    k_zero<<<2048, 256>>>();
    CvtSrcs cs = { nodes, W_in, W_out, W_r, W_z, W_t };
    k_cvt_all<<<7936, 256>>>(cs);
    k_mma<0><<<dim3(4, 64, 6), 512, SMEM_BYTES>>>(nodes, nullptr, nullptr, nullptr);
    k_dots<<<M_TOT, 128>>>(nodes, a_in_q, a_in_v, a_out_q, a_out_v);
    k_p<<<dim3(M_TOT, 2), 256>>>(mask);
    k_mma<3><<<dim3(4, 8, 16), 512, SMEM_BYTES>>>(nodes, nullptr, nullptr, nullptr);
    k_mma<1><<<dim3(4, 64, 2), 512, SMEM_BYTES>>>(nodes, b_r, b_z, nullptr);
    k_mma<2><<<dim3(4, 64, 1), 512, SMEM_BYTES>>>(nodes, b_t, nullptr, out);
}